// round 1
// baseline (speedup 1.0000x reference)
#include <cuda_runtime.h>

// ---------------- problem constants ----------------
#define NN  100000      // nodes
#define NE  3200000     // edges (without self loops)
#define NET 3300000     // edges + self loops

// ---------------- scratch (device globals; no allocation) ----------------
__device__ __align__(16) float    g_h[NN * 64];      // h of current layer
__device__ __align__(16) float    g_als[NN * 2];     // attention logits (src side)
__device__ __align__(16) float    g_ald[NN * 2];     // attention logits (dst side)
__device__ __align__(16) float    g_logit[NET * 2];  // per-edge logits, then exp(l-max)
__device__ __align__(16) unsigned g_max1[NN * 2];
__device__ __align__(16) float    g_sum1[NN * 2];
__device__ __align__(16) unsigned g_max2[NN];
__device__ __align__(16) float    g_sum2[NN];
__device__ __align__(16) float    g_acc1[NN * 64];
__device__ __align__(16) float    g_acc2[NN * 64];

// ---------------- helpers ----------------
// Monotone float<->uint key so atomicMax(unsigned) implements float max.
__device__ __forceinline__ unsigned fkey(float f) {
    unsigned b = __float_as_uint(f);
    return (b & 0x80000000u) ? ~b : (b | 0x80000000u);
}
__device__ __forceinline__ float funkey(unsigned u) {
    return (u & 0x80000000u) ? __uint_as_float(u ^ 0x80000000u) : __uint_as_float(~u);
}
__device__ __forceinline__ void red_add_v4(float* p, float a, float b, float c, float d) {
    asm volatile("red.global.add.v4.f32 [%0], {%1,%2,%3,%4};"
                 :: "l"(p), "f"(a), "f"(b), "f"(c), "f"(d) : "memory");
}

// ---------------- zero / init ----------------
__global__ void zero_kernel() {
    int stride = gridDim.x * blockDim.x;
    int i = blockIdx.x * blockDim.x + threadIdx.x;
    for (int j = i; j < NN * 64; j += stride) { g_acc1[j] = 0.f; g_acc2[j] = 0.f; }
    for (int j = i; j < NN * 2; j += stride)  { g_max1[j] = 0u;  g_sum1[j] = 0.f; }
    for (int j = i; j < NN; j += stride)      { g_max2[j] = 0u;  g_sum2[j] = 0.f; }
}

// ---------------- layer 1 node transform: h1 = [x | emb(type)] @ W1, al_s/al_d ----------------
__global__ __launch_bounds__(256) void node1_kernel(
    const float* __restrict__ x, const int* __restrict__ type_ids,
    const float* __restrict__ type_emb, const float* __restrict__ W1,
    const float* __restrict__ a_src, const float* __restrict__ a_dst)
{
    __shared__ float sW[21 * 64];
    __shared__ float sEmb[128];
    __shared__ float sX[4][5];
    __shared__ int   sT[4];
    __shared__ float sAs[64], sAd[64];

    int tid = threadIdx.y * 64 + threadIdx.x;
    for (int i = tid; i < 21 * 64; i += 256) sW[i] = W1[i];
    if (tid < 128) sEmb[tid] = type_emb[tid];
    if (tid < 64) { sAs[tid] = a_src[tid]; sAd[tid] = a_dst[tid]; }

    int node = blockIdx.x * 4 + threadIdx.y;   // NN % 4 == 0
    if (threadIdx.x < 5) sX[threadIdx.y][threadIdx.x] = x[node * 5 + threadIdx.x];
    if (threadIdx.x == 5) sT[threadIdx.y] = type_ids[node];
    __syncthreads();

    int col = threadIdx.x;
    float acc = 0.f;
#pragma unroll
    for (int k = 0; k < 5; k++) acc += sX[threadIdx.y][k] * sW[k * 64 + col];
    const float* emb = &sEmb[sT[threadIdx.y] * 16];
#pragma unroll
    for (int k = 0; k < 16; k++) acc += emb[k] * sW[(5 + k) * 64 + col];

    g_h[node * 64 + col] = acc;

    // per-head (32-col) reduction: col 0-31 = head0 warp, col 32-63 = head1 warp
    float s = acc * sAs[col], d = acc * sAd[col];
#pragma unroll
    for (int off = 16; off; off >>= 1) {
        s += __shfl_down_sync(0xffffffffu, s, off);
        d += __shfl_down_sync(0xffffffffu, d, off);
    }
    if ((col & 31) == 0) {
        int h = col >> 5;
        g_als[node * 2 + h] = s;
        g_ald[node * 2 + h] = d;
    }
}

// ---------------- layer 2 node transform: h2 = relu(acc1+b1) @ W2, al scalars ----------------
__global__ __launch_bounds__(256) void node2_kernel(
    const float* __restrict__ W2, const float* __restrict__ b1,
    const float* __restrict__ a_src, const float* __restrict__ a_dst)
{
    __shared__ float sW[64 * 64];
    __shared__ float sB[64], sAs[64], sAd[64];
    __shared__ float sIn[4][64];
    __shared__ float sPart[4][2][2];

    int tid = threadIdx.y * 64 + threadIdx.x;
    for (int i = tid; i < 4096; i += 256) sW[i] = W2[i];
    if (tid < 64) { sB[tid] = b1[tid]; sAs[tid] = a_src[tid]; sAd[tid] = a_dst[tid]; }
    __syncthreads();

    int node = blockIdx.x * 4 + threadIdx.y;
    int col = threadIdx.x;
    float v = g_acc1[node * 64 + col] + sB[col];
    v = v > 0.f ? v : 0.f;                 // relu (dropout = identity)
    sIn[threadIdx.y][col] = v;
    __syncthreads();

    float acc = 0.f;
#pragma unroll 8
    for (int k = 0; k < 64; k++) acc += sIn[threadIdx.y][k] * sW[k * 64 + col];
    g_h[node * 64 + col] = acc;

    float s = acc * sAs[col], d = acc * sAd[col];
#pragma unroll
    for (int off = 16; off; off >>= 1) {
        s += __shfl_down_sync(0xffffffffu, s, off);
        d += __shfl_down_sync(0xffffffffu, d, off);
    }
    if ((col & 31) == 0) { sPart[threadIdx.y][col >> 5][0] = s; sPart[threadIdx.y][col >> 5][1] = d; }
    __syncthreads();
    if (col == 0) {
        g_als[node] = sPart[threadIdx.y][0][0] + sPart[threadIdx.y][1][0];
        g_ald[node] = sPart[threadIdx.y][0][1] + sPart[threadIdx.y][1][1];
    }
}

// ---------------- edge pass A: logits + segment max ----------------
template <int H>
__global__ __launch_bounds__(256) void edgeA_kernel(const int* __restrict__ ei)
{
    unsigned* maxu = (H == 2) ? g_max1 : g_max2;
    int i = blockIdx.x * 256 + threadIdx.x;
    if (i >= NET) return;
    int src, dst;
    if (i < NE) { src = ei[i]; dst = ei[NE + i]; }
    else        { src = i - NE; dst = src; }
#pragma unroll
    for (int h = 0; h < H; h++) {
        float l = g_als[src * H + h] + g_ald[dst * H + h];
        l = l > 0.f ? l : 0.2f * l;        // leaky_relu(0.2)
        g_logit[i * H + h] = l;
        atomicMax(&maxu[dst * H + h], fkey(l));
    }
}

// ---------------- edge pass B: e = exp(l - max), segment sum; store e in-place ----------------
template <int H>
__global__ __launch_bounds__(256) void edgeB_kernel(const int* __restrict__ ei)
{
    const unsigned* maxu = (H == 2) ? g_max1 : g_max2;
    float* sum = (H == 2) ? g_sum1 : g_sum2;
    int i = blockIdx.x * 256 + threadIdx.x;
    if (i >= NET) return;
    int dst = (i < NE) ? ei[NE + i] : (i - NE);
#pragma unroll
    for (int h = 0; h < H; h++) {
        float m = funkey(maxu[dst * H + h]);
        float e = __expf(g_logit[i * H + h] - m);
        g_logit[i * H + h] = e;
        atomicAdd(&sum[dst * H + h], e);
    }
}

// ---------------- edge pass C: acc[dst] += alpha * h[src]  (16 lanes/edge, float4) ----------------
template <int H>
__global__ __launch_bounds__(256) void edgeC_kernel(const int* __restrict__ ei)
{
    const float* sum = (H == 2) ? g_sum1 : g_sum2;
    float* acc = (H == 2) ? g_acc1 : g_acc2;
    int t = blockIdx.x * 256 + threadIdx.x;
    int i = t >> 4;
    if (i >= NET) return;
    int lane = t & 15;
    int src, dst;
    if (i < NE) { src = ei[i]; dst = ei[NE + i]; }
    else        { src = i - NE; dst = src; }
    int head = (H == 2) ? (lane >> 3) : 0;
    float e = g_logit[i * H + head];
    float a = e / (sum[dst * H + head] + 1e-16f);
    const float4 v = *(const float4*)(g_h + src * 64 + lane * 4);
    red_add_v4(acc + dst * 64 + lane * 4, v.x * a, v.y * a, v.z * a, v.w * a);
}

// ---------------- final: bias + LayerNorm ----------------
__global__ __launch_bounds__(256) void ln_kernel(
    const float* __restrict__ b2, const float* __restrict__ gamma,
    const float* __restrict__ beta, float* __restrict__ out)
{
    int node = blockIdx.x * 8 + threadIdx.y;
    int lane = threadIdx.x;
    float v0 = g_acc2[node * 64 + lane] + b2[lane];
    float v1 = g_acc2[node * 64 + 32 + lane] + b2[32 + lane];
    float s = v0 + v1;
    float q = v0 * v0 + v1 * v1;
#pragma unroll
    for (int off = 16; off; off >>= 1) {
        s += __shfl_xor_sync(0xffffffffu, s, off);
        q += __shfl_xor_sync(0xffffffffu, q, off);
    }
    float mean = s * (1.f / 64.f);
    float var = q * (1.f / 64.f) - mean * mean;
    float inv = rsqrtf(var + 1e-5f);
    out[node * 64 + lane]      = (v0 - mean) * inv * gamma[lane] + beta[lane];
    out[node * 64 + 32 + lane] = (v1 - mean) * inv * gamma[32 + lane] + beta[32 + lane];
}

// ---------------- launch ----------------
extern "C" void kernel_launch(void* const* d_in, const int* in_sizes, int n_in,
                              void* d_out, int out_size)
{
    // Resolve inputs by element count (robust to metadata ordering).
    // Unique sizes: x=500000, edge_index=6400000, type_ids=100000, type_emb=128,
    // W1=1344, W2=4096. The eight 64-element vectors appear in order:
    // a_src1, a_dst1, b1, a_src2, a_dst2, b2, gamma, beta.
    const float* x = nullptr; const int* ei = nullptr; const int* type_ids = nullptr;
    const float* type_emb = nullptr; const float* W1 = nullptr; const float* W2 = nullptr;
    const float* v64[8] = {nullptr};
    int c64 = 0;
    for (int i = 0; i < n_in; i++) {
        switch (in_sizes[i]) {
            case 500000:  x = (const float*)d_in[i]; break;
            case 6400000: ei = (const int*)d_in[i]; break;
            case 100000:  type_ids = (const int*)d_in[i]; break;
            case 128:     type_emb = (const float*)d_in[i]; break;
            case 1344:    W1 = (const float*)d_in[i]; break;
            case 4096:    W2 = (const float*)d_in[i]; break;
            case 64:      if (c64 < 8) v64[c64++] = (const float*)d_in[i]; break;
            default: break;
        }
    }
    const float* a_src1 = v64[0]; const float* a_dst1 = v64[1]; const float* b1 = v64[2];
    const float* a_src2 = v64[3]; const float* a_dst2 = v64[4]; const float* b2 = v64[5];
    const float* gamma = v64[6];  const float* beta = v64[7];
    float* out = (float*)d_out;

    const int EB = (NET + 255) / 256;          // edge blocks (scalar passes)
    const int ECB = (NET * 16 + 255) / 256;    // edge blocks (16 lanes/edge)

    zero_kernel<<<2048, 256>>>();

    // Layer 1 (2 heads x 32 ch)
    node1_kernel<<<NN / 4, dim3(64, 4)>>>(x, type_ids, type_emb, W1, a_src1, a_dst1);
    edgeA_kernel<2><<<EB, 256>>>(ei);
    edgeB_kernel<2><<<EB, 256>>>(ei);
    edgeC_kernel<2><<<ECB, 256>>>(ei);

    // Layer 2 (1 head x 64 ch); node2 fuses bias+relu of layer-1 output
    node2_kernel<<<NN / 4, dim3(64, 4)>>>(W2, b1, a_src2, a_dst2);
    edgeA_kernel<1><<<EB, 256>>>(ei);
    edgeB_kernel<1><<<EB, 256>>>(ei);
    edgeC_kernel<1><<<ECB, 256>>>(ei);

    // Bias + LayerNorm -> output
    ln_kernel<<<NN / 8, dim3(32, 8)>>>(b2, gamma, beta, out);
}

// round 2
// speedup vs baseline: 1.3492x; 1.3492x over previous
#include <cuda_runtime.h>

// ---------------- problem constants ----------------
#define NN  100000      // nodes
#define NE  3200000     // edges (without self loops)
#define NET 3300000     // edges + self loops

// ---------------- scratch (device globals; no allocation) ----------------
__device__ __align__(16) float g_h[NN * 64];      // h of current layer
__device__ __align__(16) float g_als[NN * 2];     // attention logits (src side)
__device__ __align__(16) float g_ald[NN * 2];     // attention logits (dst side)
__device__ __align__(16) float g_sum1[NN * 2];    // per-dst sum of exp(logit), layer1
__device__ __align__(16) float g_sum2[NN];        // layer2
__device__ __align__(16) float g_acc1[NN * 64];   // unnormalized attention sums
__device__ __align__(16) float g_acc2[NN * 64];

// ---------------- helpers ----------------
__device__ __forceinline__ void red_add_v4(float* p, float a, float b, float c, float d) {
    asm volatile("red.global.add.v4.f32 [%0], {%1,%2,%3,%4};"
                 :: "l"(p), "f"(a), "f"(b), "f"(c), "f"(d) : "memory");
}
__device__ __forceinline__ void red_add_f(float* p, float v) {
    asm volatile("red.global.add.f32 [%0], %1;" :: "l"(p), "f"(v) : "memory");
}

// ---------------- zero / init ----------------
__global__ void zero_kernel() {
    int stride = gridDim.x * blockDim.x;
    int i = blockIdx.x * blockDim.x + threadIdx.x;
    for (int j = i; j < NN * 64; j += stride) { g_acc1[j] = 0.f; g_acc2[j] = 0.f; }
    for (int j = i; j < NN * 2; j += stride)  g_sum1[j] = 0.f;
    for (int j = i; j < NN; j += stride)      g_sum2[j] = 0.f;
}

// ---------------- layer 1 node transform: h1 = [x | emb(type)] @ W1, al_s/al_d ----------------
__global__ __launch_bounds__(256) void node1_kernel(
    const float* __restrict__ x, const int* __restrict__ type_ids,
    const float* __restrict__ type_emb, const float* __restrict__ W1,
    const float* __restrict__ a_src, const float* __restrict__ a_dst)
{
    __shared__ float sW[21 * 64];
    __shared__ float sEmb[128];
    __shared__ float sX[4][5];
    __shared__ int   sT[4];
    __shared__ float sAs[64], sAd[64];

    int tid = threadIdx.y * 64 + threadIdx.x;
    for (int i = tid; i < 21 * 64; i += 256) sW[i] = W1[i];
    if (tid < 128) sEmb[tid] = type_emb[tid];
    if (tid < 64) { sAs[tid] = a_src[tid]; sAd[tid] = a_dst[tid]; }

    int node = blockIdx.x * 4 + threadIdx.y;   // NN % 4 == 0
    if (threadIdx.x < 5) sX[threadIdx.y][threadIdx.x] = x[node * 5 + threadIdx.x];
    if (threadIdx.x == 5) sT[threadIdx.y] = type_ids[node];
    __syncthreads();

    int col = threadIdx.x;
    float acc = 0.f;
#pragma unroll
    for (int k = 0; k < 5; k++) acc += sX[threadIdx.y][k] * sW[k * 64 + col];
    const float* emb = &sEmb[sT[threadIdx.y] * 16];
#pragma unroll
    for (int k = 0; k < 16; k++) acc += emb[k] * sW[(5 + k) * 64 + col];

    g_h[node * 64 + col] = acc;

    // per-head (32-col) reduction: col 0-31 = head0 warp, col 32-63 = head1 warp
    float s = acc * sAs[col], d = acc * sAd[col];
#pragma unroll
    for (int off = 16; off; off >>= 1) {
        s += __shfl_down_sync(0xffffffffu, s, off);
        d += __shfl_down_sync(0xffffffffu, d, off);
    }
    if ((col & 31) == 0) {
        int h = col >> 5;
        g_als[node * 2 + h] = s;
        g_ald[node * 2 + h] = d;
    }
}

// ---------------- fused edge pass: e = exp(leaky(l)); acc[dst]+=e*h[src]; sum[dst]+=e ----------------
template <int H>
__global__ __launch_bounds__(256) void edge_kernel(const int* __restrict__ ei)
{
    float* sum = (H == 2) ? g_sum1 : g_sum2;
    float* acc = (H == 2) ? g_acc1 : g_acc2;
    int t = blockIdx.x * 256 + threadIdx.x;
    int i = t >> 4;
    if (i >= NET) return;
    int lane = t & 15;
    int src, dst;
    if (i < NE) { src = __ldg(ei + i); dst = __ldg(ei + NE + i); }
    else        { src = i - NE; dst = src; }
    int head = (H == 2) ? (lane >> 3) : 0;
    float l = g_als[src * H + head] + g_ald[dst * H + head];
    l = l > 0.f ? l : 0.2f * l;          // leaky_relu(0.2)
    float e = __expf(l);                 // no max-subtraction: logits are bounded
    const float4 v = *(const float4*)(g_h + src * 64 + lane * 4);
    red_add_v4(acc + dst * 64 + lane * 4, v.x * e, v.y * e, v.z * e, v.w * e);
    if ((lane & 7) == 0 && (H == 2 || lane == 0))
        red_add_f(&sum[dst * H + head], e);
}

// ---------------- layer 2 node transform: h2 = relu(acc1/sum1 + b1) @ W2 ----------------
__global__ __launch_bounds__(256) void node2_kernel(
    const float* __restrict__ W2, const float* __restrict__ b1,
    const float* __restrict__ a_src, const float* __restrict__ a_dst)
{
    __shared__ float sW[64 * 64];
    __shared__ float sB[64], sAs[64], sAd[64];
    __shared__ float sIn[4][64];
    __shared__ float sPart[4][2][2];

    int tid = threadIdx.y * 64 + threadIdx.x;
    for (int i = tid; i < 4096; i += 256) sW[i] = W2[i];
    if (tid < 64) { sB[tid] = b1[tid]; sAs[tid] = a_src[tid]; sAd[tid] = a_dst[tid]; }
    __syncthreads();

    int node = blockIdx.x * 4 + threadIdx.y;
    int col = threadIdx.x;
    float inv = 1.f / (g_sum1[node * 2 + (col >> 5)] + 1e-16f);
    float v = g_acc1[node * 64 + col] * inv + sB[col];
    v = v > 0.f ? v : 0.f;               // relu (dropout = identity)
    sIn[threadIdx.y][col] = v;
    __syncthreads();

    float acc = 0.f;
#pragma unroll 8
    for (int k = 0; k < 64; k++) acc += sIn[threadIdx.y][k] * sW[k * 64 + col];
    g_h[node * 64 + col] = acc;

    float s = acc * sAs[col], d = acc * sAd[col];
#pragma unroll
    for (int off = 16; off; off >>= 1) {
        s += __shfl_down_sync(0xffffffffu, s, off);
        d += __shfl_down_sync(0xffffffffu, d, off);
    }
    if ((col & 31) == 0) { sPart[threadIdx.y][col >> 5][0] = s; sPart[threadIdx.y][col >> 5][1] = d; }
    __syncthreads();
    if (col == 0) {
        g_als[node] = sPart[threadIdx.y][0][0] + sPart[threadIdx.y][1][0];
        g_ald[node] = sPart[threadIdx.y][0][1] + sPart[threadIdx.y][1][1];
    }
}

// ---------------- final: normalize + bias + LayerNorm ----------------
__global__ __launch_bounds__(256) void ln_kernel(
    const float* __restrict__ b2, const float* __restrict__ gamma,
    const float* __restrict__ beta, float* __restrict__ out)
{
    int node = blockIdx.x * 8 + threadIdx.y;
    int lane = threadIdx.x;
    float invs = 1.f / (g_sum2[node] + 1e-16f);
    float v0 = g_acc2[node * 64 + lane] * invs + b2[lane];
    float v1 = g_acc2[node * 64 + 32 + lane] * invs + b2[32 + lane];
    float s = v0 + v1;
    float q = v0 * v0 + v1 * v1;
#pragma unroll
    for (int off = 16; off; off >>= 1) {
        s += __shfl_xor_sync(0xffffffffu, s, off);
        q += __shfl_xor_sync(0xffffffffu, q, off);
    }
    float mean = s * (1.f / 64.f);
    float var = q * (1.f / 64.f) - mean * mean;
    float inv = rsqrtf(var + 1e-5f);
    out[node * 64 + lane]      = (v0 - mean) * inv * gamma[lane] + beta[lane];
    out[node * 64 + 32 + lane] = (v1 - mean) * inv * gamma[32 + lane] + beta[32 + lane];
}

// ---------------- launch ----------------
extern "C" void kernel_launch(void* const* d_in, const int* in_sizes, int n_in,
                              void* d_out, int out_size)
{
    const float* x = nullptr; const int* ei = nullptr; const int* type_ids = nullptr;
    const float* type_emb = nullptr; const float* W1 = nullptr; const float* W2 = nullptr;
    const float* v64[8] = {nullptr};
    int c64 = 0;
    for (int i = 0; i < n_in; i++) {
        switch (in_sizes[i]) {
            case 500000:  x = (const float*)d_in[i]; break;
            case 6400000: ei = (const int*)d_in[i]; break;
            case 100000:  type_ids = (const int*)d_in[i]; break;
            case 128:     type_emb = (const float*)d_in[i]; break;
            case 1344:    W1 = (const float*)d_in[i]; break;
            case 4096:    W2 = (const float*)d_in[i]; break;
            case 64:      if (c64 < 8) v64[c64++] = (const float*)d_in[i]; break;
            default: break;
        }
    }
    const float* a_src1 = v64[0]; const float* a_dst1 = v64[1]; const float* b1 = v64[2];
    const float* a_src2 = v64[3]; const float* a_dst2 = v64[4]; const float* b2 = v64[5];
    const float* gamma = v64[6];  const float* beta = v64[7];
    float* out = (float*)d_out;

    const long long ET = (long long)NET * 16;
    const int ECB = (int)((ET + 255) / 256);   // 16 lanes per edge

    zero_kernel<<<2048, 256>>>();

    // Layer 1 (2 heads x 32 ch): node transform + single fused edge pass
    node1_kernel<<<NN / 4, dim3(64, 4)>>>(x, type_ids, type_emb, W1, a_src1, a_dst1);
    edge_kernel<2><<<ECB, 256>>>(ei);

    // Layer 2 (1 head x 64 ch): normalization fused into node2
    node2_kernel<<<NN / 4, dim3(64, 4)>>>(W2, b1, a_src2, a_dst2);
    edge_kernel<1><<<ECB, 256>>>(ei);

    // Normalize + bias + LayerNorm -> output
    ln_kernel<<<NN / 8, dim3(32, 8)>>>(b2, gamma, beta, out);
}

// round 4
// speedup vs baseline: 1.5077x; 1.1175x over previous
#include <cuda_runtime.h>
#include <cuda_fp16.h>

// ---------------- problem constants ----------------
#define NN  100000      // nodes
#define NE  3200000     // edges (without self loops)
#define NET 3300000     // edges + self loops

// ---------------- scratch (device globals; no allocation) ----------------
__device__ __align__(16) __half g_h[NN * 64];     // h of current layer (fp16 storage)
__device__ __align__(16) float g_als[NN * 2];     // attention logits (src side)
__device__ __align__(16) float g_ald[NN * 2];     // attention logits (dst side)
__device__ __align__(16) float g_sum1[NN * 2];    // per-dst sum of exp(logit), layer1
__device__ __align__(16) float g_sum2[NN];        // layer2
__device__ __align__(16) float g_acc1[NN * 64];   // unnormalized attention sums
__device__ __align__(16) float g_acc2[NN * 64];
__device__ __align__(16) float g_wa_s[64];        // W2 @ a_src2
__device__ __align__(16) float g_wa_d[64];        // W2 @ a_dst2

// ---------------- helpers ----------------
__device__ __forceinline__ void red_add_v4(float* p, float a, float b, float c, float d) {
    asm volatile("red.global.add.v4.f32 [%0], {%1,%2,%3,%4};"
                 :: "l"(p), "f"(a), "f"(b), "f"(c), "f"(d) : "memory");
}
__device__ __forceinline__ void red_add_f(float* p, float v) {
    asm volatile("red.global.add.f32 [%0], %1;" :: "l"(p), "f"(v) : "memory");
}

// ---------------- prep: Wa = W2 @ a  (64x64 @ 64 -> 64, twice) ----------------
__global__ void prep_kernel(const float* __restrict__ W2,
                            const float* __restrict__ a_src, const float* __restrict__ a_dst)
{
    int k = threadIdx.x;   // 64 threads
    float s = 0.f, d = 0.f;
#pragma unroll 8
    for (int c = 0; c < 64; c++) {
        float w = W2[k * 64 + c];
        s += w * a_src[c];
        d += w * a_dst[c];
    }
    g_wa_s[k] = s;
    g_wa_d[k] = d;
}

// ---------------- layer 1 node transform (also zeroes acc1/sum1) ----------------
__global__ __launch_bounds__(256) void node1_kernel(
    const float* __restrict__ x, const int* __restrict__ type_ids,
    const float* __restrict__ type_emb, const float* __restrict__ W1,
    const float* __restrict__ a_src, const float* __restrict__ a_dst)
{
    __shared__ float sW[21 * 64];
    __shared__ float sEmb[128];
    __shared__ float sX[4][5];
    __shared__ int   sT[4];
    __shared__ float sAs[64], sAd[64];

    int tid = threadIdx.y * 64 + threadIdx.x;
    for (int i = tid; i < 21 * 64; i += 256) sW[i] = W1[i];
    if (tid < 128) sEmb[tid] = type_emb[tid];
    if (tid < 64) { sAs[tid] = a_src[tid]; sAd[tid] = a_dst[tid]; }

    int node = blockIdx.x * 4 + threadIdx.y;   // NN % 4 == 0
    if (threadIdx.x < 5) sX[threadIdx.y][threadIdx.x] = x[node * 5 + threadIdx.x];
    if (threadIdx.x == 5) sT[threadIdx.y] = type_ids[node];
    __syncthreads();

    int col = threadIdx.x;
    float acc = 0.f;
#pragma unroll
    for (int k = 0; k < 5; k++) acc += sX[threadIdx.y][k] * sW[k * 64 + col];
    const float* emb = &sEmb[sT[threadIdx.y] * 16];
#pragma unroll
    for (int k = 0; k < 16; k++) acc += emb[k] * sW[(5 + k) * 64 + col];

    // store h as fp16 (pack pairs via shfl; (2c,2c+1) always within one warp)
    float nxt = __shfl_down_sync(0xffffffffu, acc, 1);
    if ((col & 1) == 0) {
        __half2 p = __floats2half2_rn(acc, nxt);
        *(__half2*)(g_h + node * 64 + col) = p;
    }

    // zero accumulators for the upcoming edge pass
    g_acc1[node * 64 + col] = 0.f;
    if (col < 2) g_sum1[node * 2 + col] = 0.f;

    // per-head (32-col) reduction: col 0-31 = head0 warp, col 32-63 = head1 warp
    float s = acc * sAs[col], d = acc * sAd[col];
#pragma unroll
    for (int off = 16; off; off >>= 1) {
        s += __shfl_down_sync(0xffffffffu, s, off);
        d += __shfl_down_sync(0xffffffffu, d, off);
    }
    if ((col & 31) == 0) {
        int h = col >> 5;
        g_als[node * 2 + h] = s;
        g_ald[node * 2 + h] = d;
    }
}

// ---------------- fused edge pass: e = exp(leaky(l)); acc[dst]+=e*h[src]; sum[dst]+=e ----------------
template <int H>
__global__ __launch_bounds__(256) void edge_kernel(const int* __restrict__ ei)
{
    float* sum = (H == 2) ? g_sum1 : g_sum2;
    float* acc = (H == 2) ? g_acc1 : g_acc2;
    int t = blockIdx.x * 256 + threadIdx.x;
    int i = t >> 4;
    if (i >= NET) return;
    int lane = t & 15;
    int src, dst;
    if (i < NE) { src = __ldg(ei + i); dst = __ldg(ei + NE + i); }
    else        { src = i - NE; dst = src; }
    int head = (H == 2) ? (lane >> 3) : 0;
    float l = g_als[src * H + head] + g_ald[dst * H + head];
    l = l > 0.f ? l : 0.2f * l;          // leaky_relu(0.2)
    float e = __expf(l);                 // no max-subtraction: logits are bounded
    // gather 4 fp16 channels (8B per lane, 128B per edge)
    uint2 raw = *(const uint2*)(g_h + src * 64 + lane * 4);
    float2 f0 = __half22float2(*(__half2*)&raw.x);
    float2 f1 = __half22float2(*(__half2*)&raw.y);
    red_add_v4(acc + dst * 64 + lane * 4, f0.x * e, f0.y * e, f1.x * e, f1.y * e);
    if ((lane & 7) == 0 && (H == 2 || lane == 0))
        red_add_f(&sum[dst * H + head], e);
}

// ---------------- layer 2 node transform: h2 = relu(acc1/sum1 + b1) @ W2 ----------------
// Register-tiled: 256 threads, 64 nodes/block; thread = 4 nodes x 4 cols.
// Also zeroes acc2/sum2 and computes als/ald via precomputed Wa vectors.
__global__ __launch_bounds__(256) void node2_kernel(const float* __restrict__ W2,
                                                    const float* __restrict__ b1)
{
    __shared__ float sW[64 * 64];          // 16 KB
    __shared__ float sIn[64 * 68];         // 64 nodes x 64 k, stride 68 (pad)
    __shared__ float sWaS[64], sWaD[64], sB[64];

    int tid = threadIdx.x;
    int nbase = blockIdx.x * 64;

    for (int i = tid; i < 4096; i += 256) sW[i] = W2[i];
    if (tid < 64) { sWaS[tid] = g_wa_s[tid]; sWaD[tid] = g_wa_d[tid]; sB[tid] = b1[tid]; }
    __syncthreads();   // sB (and sWaS/sWaD) must be visible before the sIn build below

    // build sIn = relu(acc1/sum1 + b1); zero acc2/sum2 on the way
    for (int i = tid; i < 4096; i += 256) {
        int n = nbase + (i >> 6);
        int c = i & 63;
        float v = 0.f;
        if (n < NN) {
            float inv = 1.f / (g_sum1[n * 2 + (c >> 5)] + 1e-16f);
            v = g_acc1[n * 64 + c] * inv + sB[c];
            v = v > 0.f ? v : 0.f;
            g_acc2[n * 64 + c] = 0.f;
        }
        sIn[(i >> 6) * 68 + c] = v;
    }
    if (tid < 64 && nbase + tid < NN) g_sum2[nbase + tid] = 0.f;
    __syncthreads();

    int cg = tid & 15;    // 4 output cols: cg*4 ..
    int ng = tid >> 4;    // 4 nodes: ng*4 ..

    float acc[4][4];
#pragma unroll
    for (int j = 0; j < 4; j++)
#pragma unroll
        for (int c = 0; c < 4; c++) acc[j][c] = 0.f;
    float als[4] = {0.f, 0.f, 0.f, 0.f}, ald[4] = {0.f, 0.f, 0.f, 0.f};

#pragma unroll 4
    for (int k4 = 0; k4 < 16; k4++) {
        float in[4][4];
#pragma unroll
        for (int j = 0; j < 4; j++) {
            float4 v = *(const float4*)&sIn[(ng * 4 + j) * 68 + k4 * 4];
            in[j][0] = v.x; in[j][1] = v.y; in[j][2] = v.z; in[j][3] = v.w;
        }
#pragma unroll
        for (int kk = 0; kk < 4; kk++) {
            float4 w = *(const float4*)&sW[(k4 * 4 + kk) * 64 + cg * 4];
#pragma unroll
            for (int j = 0; j < 4; j++) {
                acc[j][0] += in[j][kk] * w.x;
                acc[j][1] += in[j][kk] * w.y;
                acc[j][2] += in[j][kk] * w.z;
                acc[j][3] += in[j][kk] * w.w;
            }
        }
        if (cg == 0) {
#pragma unroll
            for (int kk = 0; kk < 4; kk++) {
                float ws = sWaS[k4 * 4 + kk], wd = sWaD[k4 * 4 + kk];
#pragma unroll
                for (int j = 0; j < 4; j++) {
                    als[j] += in[j][kk] * ws;
                    ald[j] += in[j][kk] * wd;
                }
            }
        }
    }

    // write h (fp16) and attention logits
#pragma unroll
    for (int j = 0; j < 4; j++) {
        int n = nbase + ng * 4 + j;
        if (n >= NN) continue;
        __half2 p0 = __floats2half2_rn(acc[j][0], acc[j][1]);
        __half2 p1 = __floats2half2_rn(acc[j][2], acc[j][3]);
        uint2 raw;
        raw.x = *(unsigned*)&p0;
        raw.y = *(unsigned*)&p1;
        *(uint2*)(g_h + n * 64 + cg * 4) = raw;
        if (cg == 0) { g_als[n] = als[j]; g_ald[n] = ald[j]; }
    }
}

// ---------------- final: normalize + bias + LayerNorm ----------------
__global__ __launch_bounds__(256) void ln_kernel(
    const float* __restrict__ b2, const float* __restrict__ gamma,
    const float* __restrict__ beta, float* __restrict__ out)
{
    int node = blockIdx.x * 8 + threadIdx.y;
    int lane = threadIdx.x;
    float invs = 1.f / (g_sum2[node] + 1e-16f);
    float v0 = g_acc2[node * 64 + lane] * invs + b2[lane];
    float v1 = g_acc2[node * 64 + 32 + lane] * invs + b2[32 + lane];
    float s = v0 + v1;
    float q = v0 * v0 + v1 * v1;
#pragma unroll
    for (int off = 16; off; off >>= 1) {
        s += __shfl_xor_sync(0xffffffffu, s, off);
        q += __shfl_xor_sync(0xffffffffu, q, off);
    }
    float mean = s * (1.f / 64.f);
    float var = q * (1.f / 64.f) - mean * mean;
    float inv = rsqrtf(var + 1e-5f);
    out[node * 64 + lane]      = (v0 - mean) * inv * gamma[lane] + beta[lane];
    out[node * 64 + 32 + lane] = (v1 - mean) * inv * gamma[32 + lane] + beta[32 + lane];
}

// ---------------- launch ----------------
extern "C" void kernel_launch(void* const* d_in, const int* in_sizes, int n_in,
                              void* d_out, int out_size)
{
    const float* x = nullptr; const int* ei = nullptr; const int* type_ids = nullptr;
    const float* type_emb = nullptr; const float* W1 = nullptr; const float* W2 = nullptr;
    const float* v64[8] = {nullptr};
    int c64 = 0;
    for (int i = 0; i < n_in; i++) {
        switch (in_sizes[i]) {
            case 500000:  x = (const float*)d_in[i]; break;
            case 6400000: ei = (const int*)d_in[i]; break;
            case 100000:  type_ids = (const int*)d_in[i]; break;
            case 128:     type_emb = (const float*)d_in[i]; break;
            case 1344:    W1 = (const float*)d_in[i]; break;
            case 4096:    W2 = (const float*)d_in[i]; break;
            case 64:      if (c64 < 8) v64[c64++] = (const float*)d_in[i]; break;
            default: break;
        }
    }
    const float* a_src1 = v64[0]; const float* a_dst1 = v64[1]; const float* b1 = v64[2];
    const float* a_src2 = v64[3]; const float* a_dst2 = v64[4]; const float* b2 = v64[5];
    const float* gamma = v64[6];  const float* beta = v64[7];
    float* out = (float*)d_out;

    const long long ET = (long long)NET * 16;
    const int ECB = (int)((ET + 255) / 256);   // 16 lanes per edge

    prep_kernel<<<1, 64>>>(W2, a_src2, a_dst2);

    // Layer 1 (2 heads x 32 ch): node transform (zeroes acc1/sum1) + fused edge pass
    node1_kernel<<<NN / 4, dim3(64, 4)>>>(x, type_ids, type_emb, W1, a_src1, a_dst1);
    edge_kernel<2><<<ECB, 256>>>(ei);

    // Layer 2 (1 head x 64 ch): register-tiled GEMM, zeroes acc2/sum2
    node2_kernel<<<(NN + 63) / 64, 256>>>(W2, b1);
    edge_kernel<1><<<ECB, 256>>>(ei);

    // Normalize + bias + LayerNorm -> output
    ln_kernel<<<NN / 8, dim3(32, 8)>>>(b2, gamma, beta, out);
}

// round 5
// speedup vs baseline: 2.6402x; 1.7511x over previous
#include <cuda_runtime.h>
#include <cuda_fp16.h>

// ---------------- problem constants ----------------
#define NN  100000      // nodes
#define NE  3200000     // edges (without self loops)
#define SB  512
#define NB1 196         // ceil(NN / SB)

// ---------------- scratch (device globals; no allocation) ----------------
__device__ __align__(16) __half g_h[NN * 64];     // h of current layer (fp16, gathered by edges)
__device__ __align__(16) float  g_h2f[NN * 64];   // layer-2 GEMM input (relu(norm+b1)), fp32
__device__ __align__(16) float  g_acc2[NN * 64];  // layer-2 normalized output
__device__ __align__(16) float  g_als[NN * 2];    // attention logits (src side)
__device__ __align__(16) float  g_ald[NN * 2];    // attention logits (dst side)
__device__ __align__(16) float  g_wa_s[64];       // W2 @ a_src2
__device__ __align__(16) float  g_wa_d[64];       // W2 @ a_dst2
// CSR build
__device__ int g_cnt[NN];
__device__ int g_start[NN];
__device__ int g_cur[NN];
__device__ int g_bsum[NB1];
__device__ int g_bpre[NB1];
__device__ int g_csr[NE];

// ================= CSR build =================
__global__ void hist_zero_kernel() {
    int i = blockIdx.x * SB + threadIdx.x;
    if (i < NN) g_cnt[i] = 0;
}
__global__ void hist_kernel(const int* __restrict__ ei) {
    int i = blockIdx.x * SB + threadIdx.x;
    if (i < NE) atomicAdd(&g_cnt[__ldg(ei + NE + i)], 1);
}
__global__ void scan1_kernel() {
    __shared__ int s[SB];
    int t = threadIdx.x;
    int i = blockIdx.x * SB + t;
    int v = (i < NN) ? g_cnt[i] : 0;
    s[t] = v;
    __syncthreads();
#pragma unroll
    for (int off = 1; off < SB; off <<= 1) {
        int u = (t >= off) ? s[t - off] : 0;
        __syncthreads();
        s[t] += u;
        __syncthreads();
    }
    if (i < NN) g_start[i] = s[t] - v;        // exclusive within block
    if (t == SB - 1) g_bsum[blockIdx.x] = s[t];
}
__global__ void scan2_kernel() {
    __shared__ int s[256];
    int t = threadIdx.x;
    int v = (t < NB1) ? g_bsum[t] : 0;
    s[t] = v;
    __syncthreads();
#pragma unroll
    for (int off = 1; off < 256; off <<= 1) {
        int u = (t >= off) ? s[t - off] : 0;
        __syncthreads();
        s[t] += u;
        __syncthreads();
    }
    if (t < NB1) g_bpre[t] = s[t] - v;        // exclusive block prefix
}
__global__ void scan3_kernel() {
    int i = blockIdx.x * SB + threadIdx.x;
    if (i < NN) {
        int st = g_start[i] + g_bpre[blockIdx.x];
        g_start[i] = st;
        g_cur[i] = st;
    }
}
__global__ void fill_kernel(const int* __restrict__ ei) {
    int i = blockIdx.x * SB + threadIdx.x;
    if (i < NE) {
        int dst = __ldg(ei + NE + i);
        int src = __ldg(ei + i);
        int pos = atomicAdd(&g_cur[dst], 1);
        g_csr[pos] = src;
    }
}

// ================= prep: Wa = W2 @ a =================
__global__ void prep_kernel(const float* __restrict__ W2,
                            const float* __restrict__ a_src, const float* __restrict__ a_dst)
{
    int k = threadIdx.x;   // 64 threads
    float s = 0.f, d = 0.f;
#pragma unroll 8
    for (int c = 0; c < 64; c++) {
        float w = W2[k * 64 + c];
        s += w * a_src[c];
        d += w * a_dst[c];
    }
    g_wa_s[k] = s;
    g_wa_d[k] = d;
}

// ================= layer 1 node transform =================
__global__ __launch_bounds__(256) void node1_kernel(
    const float* __restrict__ x, const int* __restrict__ type_ids,
    const float* __restrict__ type_emb, const float* __restrict__ W1,
    const float* __restrict__ a_src, const float* __restrict__ a_dst)
{
    __shared__ float sW[21 * 64];
    __shared__ float sEmb[128];
    __shared__ float sX[4][5];
    __shared__ int   sT[4];
    __shared__ float sAs[64], sAd[64];

    int tid = threadIdx.y * 64 + threadIdx.x;
    for (int i = tid; i < 21 * 64; i += 256) sW[i] = W1[i];
    if (tid < 128) sEmb[tid] = type_emb[tid];
    if (tid < 64) { sAs[tid] = a_src[tid]; sAd[tid] = a_dst[tid]; }

    int node = blockIdx.x * 4 + threadIdx.y;   // NN % 4 == 0
    if (threadIdx.x < 5) sX[threadIdx.y][threadIdx.x] = x[node * 5 + threadIdx.x];
    if (threadIdx.x == 5) sT[threadIdx.y] = type_ids[node];
    __syncthreads();

    int col = threadIdx.x;
    float acc = 0.f;
#pragma unroll
    for (int k = 0; k < 5; k++) acc += sX[threadIdx.y][k] * sW[k * 64 + col];
    const float* emb = &sEmb[sT[threadIdx.y] * 16];
#pragma unroll
    for (int k = 0; k < 16; k++) acc += emb[k] * sW[(5 + k) * 64 + col];

    // store h as fp16 (pack pairs via shfl; (2c,2c+1) always within one warp)
    float nxt = __shfl_down_sync(0xffffffffu, acc, 1);
    if ((col & 1) == 0) {
        __half2 p = __floats2half2_rn(acc, nxt);
        *(__half2*)(g_h + node * 64 + col) = p;
    }

    // per-head (32-col) reduction: col 0-31 = head0 warp, col 32-63 = head1 warp
    float s = acc * sAs[col], d = acc * sAd[col];
#pragma unroll
    for (int off = 16; off; off >>= 1) {
        s += __shfl_down_sync(0xffffffffu, s, off);
        d += __shfl_down_sync(0xffffffffu, d, off);
    }
    if ((col & 31) == 0) {
        int h = col >> 5;
        g_als[node * 2 + h] = s;
        g_ald[node * 2 + h] = d;
    }
}

// ================= CSR edge pass (gather-only, atomic-free) =================
// 16 lanes per dst node; loop in-edges, accumulate in registers, write normalized
// result once. Layer1 (H=2): fuse +b1, relu -> g_h2f. Layer2 (H=1): -> g_acc2.
template <int H>
__global__ __launch_bounds__(256) void edge_csr_kernel(const float* __restrict__ b1)
{
    int lane = threadIdx.x & 15;
    int dst  = blockIdx.x * 16 + (threadIdx.x >> 4);
    if (dst >= NN) return;
    int base = __ldg(&g_start[dst]);
    int deg  = __ldg(&g_cnt[dst]);
    int head = (H == 2) ? (lane >> 3) : 0;
    float adh = (H == 2) ? g_ald[dst * 2 + head] : g_ald[dst];

    float a0 = 0.f, a1 = 0.f, a2 = 0.f, a3 = 0.f, esum = 0.f;

    // self loop
    {
        float l = ((H == 2) ? g_als[dst * 2 + head] : g_als[dst]) + adh;
        l = l > 0.f ? l : 0.2f * l;
        float e = __expf(l);
        uint2 r = *(const uint2*)(g_h + dst * 64 + lane * 4);
        float2 f0 = __half22float2(*(__half2*)&r.x);
        float2 f1 = __half22float2(*(__half2*)&r.y);
        a0 += e * f0.x; a1 += e * f0.y; a2 += e * f1.x; a3 += e * f1.y;
        esum += e;
    }

    int j = base, end = base + deg;
    // unroll x4: batch independent loads for MLP
    for (; j + 4 <= end; j += 4) {
        int s0 = __ldg(g_csr + j);
        int s1 = __ldg(g_csr + j + 1);
        int s2 = __ldg(g_csr + j + 2);
        int s3 = __ldg(g_csr + j + 3);
        float l0 = ((H == 2) ? __ldg(g_als + s0 * 2 + head) : __ldg(g_als + s0)) + adh;
        float l1 = ((H == 2) ? __ldg(g_als + s1 * 2 + head) : __ldg(g_als + s1)) + adh;
        float l2 = ((H == 2) ? __ldg(g_als + s2 * 2 + head) : __ldg(g_als + s2)) + adh;
        float l3 = ((H == 2) ? __ldg(g_als + s3 * 2 + head) : __ldg(g_als + s3)) + adh;
        uint2 r0 = *(const uint2*)(g_h + s0 * 64 + lane * 4);
        uint2 r1 = *(const uint2*)(g_h + s1 * 64 + lane * 4);
        uint2 r2 = *(const uint2*)(g_h + s2 * 64 + lane * 4);
        uint2 r3 = *(const uint2*)(g_h + s3 * 64 + lane * 4);
        l0 = l0 > 0.f ? l0 : 0.2f * l0;  float e0 = __expf(l0);
        l1 = l1 > 0.f ? l1 : 0.2f * l1;  float e1 = __expf(l1);
        l2 = l2 > 0.f ? l2 : 0.2f * l2;  float e2 = __expf(l2);
        l3 = l3 > 0.f ? l3 : 0.2f * l3;  float e3 = __expf(l3);
        float2 f;
        f = __half22float2(*(__half2*)&r0.x); a0 += e0 * f.x; a1 += e0 * f.y;
        f = __half22float2(*(__half2*)&r0.y); a2 += e0 * f.x; a3 += e0 * f.y;
        f = __half22float2(*(__half2*)&r1.x); a0 += e1 * f.x; a1 += e1 * f.y;
        f = __half22float2(*(__half2*)&r1.y); a2 += e1 * f.x; a3 += e1 * f.y;
        f = __half22float2(*(__half2*)&r2.x); a0 += e2 * f.x; a1 += e2 * f.y;
        f = __half22float2(*(__half2*)&r2.y); a2 += e2 * f.x; a3 += e2 * f.y;
        f = __half22float2(*(__half2*)&r3.x); a0 += e3 * f.x; a1 += e3 * f.y;
        f = __half22float2(*(__half2*)&r3.y); a2 += e3 * f.x; a3 += e3 * f.y;
        esum += e0 + e1 + e2 + e3;
    }
    for (; j < end; j++) {
        int s = __ldg(g_csr + j);
        float l = ((H == 2) ? __ldg(g_als + s * 2 + head) : __ldg(g_als + s)) + adh;
        l = l > 0.f ? l : 0.2f * l;
        float e = __expf(l);
        uint2 r = *(const uint2*)(g_h + s * 64 + lane * 4);
        float2 f0 = __half22float2(*(__half2*)&r.x);
        float2 f1 = __half22float2(*(__half2*)&r.y);
        a0 += e * f0.x; a1 += e * f0.y; a2 += e * f1.x; a3 += e * f1.y;
        esum += e;
    }

    float inv = 1.f / (esum + 1e-16f);
    if (H == 2) {
        float4 b = *(const float4*)(b1 + lane * 4);
        float4 o;
        o.x = fmaxf(a0 * inv + b.x, 0.f);
        o.y = fmaxf(a1 * inv + b.y, 0.f);
        o.z = fmaxf(a2 * inv + b.z, 0.f);
        o.w = fmaxf(a3 * inv + b.w, 0.f);
        *(float4*)(g_h2f + dst * 64 + lane * 4) = o;
    } else {
        *(float4*)(g_acc2 + dst * 64 + lane * 4) = make_float4(a0 * inv, a1 * inv, a2 * inv, a3 * inv);
    }
}

// ================= layer 2 node transform: h2 = g_h2f @ W2 =================
// Register-tiled: 256 threads, 64 nodes/block; thread = 4 nodes x 4 cols.
__global__ __launch_bounds__(256) void node2_kernel(const float* __restrict__ W2)
{
    __shared__ float sW[64 * 64];          // 16 KB
    __shared__ float sIn[64 * 68];         // 64 nodes x 64 k, stride 68 (pad)
    __shared__ float sWaS[64], sWaD[64];

    int tid = threadIdx.x;
    int nbase = blockIdx.x * 64;

    for (int i = tid; i < 4096; i += 256) sW[i] = W2[i];
    if (tid < 64) { sWaS[tid] = g_wa_s[tid]; sWaD[tid] = g_wa_d[tid]; }

    // stage inputs (already relu(norm + b1), fp32)
    for (int i = tid; i < 1024; i += 256) {   // 64 nodes x 16 float4
        int n = i >> 4, c4 = i & 15;
        int gn = nbase + n;
        float4 v = make_float4(0.f, 0.f, 0.f, 0.f);
        if (gn < NN) v = *(const float4*)(g_h2f + gn * 64 + c4 * 4);
        *(float4*)&sIn[n * 68 + c4 * 4] = v;
    }
    __syncthreads();

    int cg = tid & 15;    // 4 output cols: cg*4 ..
    int ng = tid >> 4;    // 4 nodes: ng*4 ..

    float acc[4][4];
#pragma unroll
    for (int j = 0; j < 4; j++)
#pragma unroll
        for (int c = 0; c < 4; c++) acc[j][c] = 0.f;
    float als[4] = {0.f, 0.f, 0.f, 0.f}, ald[4] = {0.f, 0.f, 0.f, 0.f};

#pragma unroll 4
    for (int k4 = 0; k4 < 16; k4++) {
        float in[4][4];
#pragma unroll
        for (int j = 0; j < 4; j++) {
            float4 v = *(const float4*)&sIn[(ng * 4 + j) * 68 + k4 * 4];
            in[j][0] = v.x; in[j][1] = v.y; in[j][2] = v.z; in[j][3] = v.w;
        }
#pragma unroll
        for (int kk = 0; kk < 4; kk++) {
            float4 w = *(const float4*)&sW[(k4 * 4 + kk) * 64 + cg * 4];
#pragma unroll
            for (int j = 0; j < 4; j++) {
                acc[j][0] += in[j][kk] * w.x;
                acc[j][1] += in[j][kk] * w.y;
                acc[j][2] += in[j][kk] * w.z;
                acc[j][3] += in[j][kk] * w.w;
            }
        }
        if (cg == 0) {
#pragma unroll
            for (int kk = 0; kk < 4; kk++) {
                float ws = sWaS[k4 * 4 + kk], wd = sWaD[k4 * 4 + kk];
#pragma unroll
                for (int j = 0; j < 4; j++) {
                    als[j] += in[j][kk] * ws;
                    ald[j] += in[j][kk] * wd;
                }
            }
        }
    }

    // write h (fp16) and attention logits
#pragma unroll
    for (int j = 0; j < 4; j++) {
        int n = nbase + ng * 4 + j;
        if (n >= NN) continue;
        __half2 p0 = __floats2half2_rn(acc[j][0], acc[j][1]);
        __half2 p1 = __floats2half2_rn(acc[j][2], acc[j][3]);
        uint2 raw;
        raw.x = *(unsigned*)&p0;
        raw.y = *(unsigned*)&p1;
        *(uint2*)(g_h + n * 64 + cg * 4) = raw;
        if (cg == 0) { g_als[n] = als[j]; g_ald[n] = ald[j]; }
    }
}

// ================= final: bias + LayerNorm =================
__global__ __launch_bounds__(256) void ln_kernel(
    const float* __restrict__ b2, const float* __restrict__ gamma,
    const float* __restrict__ beta, float* __restrict__ out)
{
    int node = blockIdx.x * 8 + threadIdx.y;
    int lane = threadIdx.x;
    float v0 = g_acc2[node * 64 + lane] + b2[lane];
    float v1 = g_acc2[node * 64 + 32 + lane] + b2[32 + lane];
    float s = v0 + v1;
    float q = v0 * v0 + v1 * v1;
#pragma unroll
    for (int off = 16; off; off >>= 1) {
        s += __shfl_xor_sync(0xffffffffu, s, off);
        q += __shfl_xor_sync(0xffffffffu, q, off);
    }
    float mean = s * (1.f / 64.f);
    float var = q * (1.f / 64.f) - mean * mean;
    float inv = rsqrtf(var + 1e-5f);
    out[node * 64 + lane]      = (v0 - mean) * inv * gamma[lane] + beta[lane];
    out[node * 64 + 32 + lane] = (v1 - mean) * inv * gamma[32 + lane] + beta[32 + lane];
}

// ================= launch =================
extern "C" void kernel_launch(void* const* d_in, const int* in_sizes, int n_in,
                              void* d_out, int out_size)
{
    const float* x = nullptr; const int* ei = nullptr; const int* type_ids = nullptr;
    const float* type_emb = nullptr; const float* W1 = nullptr; const float* W2 = nullptr;
    const float* v64[8] = {nullptr};
    int c64 = 0;
    for (int i = 0; i < n_in; i++) {
        switch (in_sizes[i]) {
            case 500000:  x = (const float*)d_in[i]; break;
            case 6400000: ei = (const int*)d_in[i]; break;
            case 100000:  type_ids = (const int*)d_in[i]; break;
            case 128:     type_emb = (const float*)d_in[i]; break;
            case 1344:    W1 = (const float*)d_in[i]; break;
            case 4096:    W2 = (const float*)d_in[i]; break;
            case 64:      if (c64 < 8) v64[c64++] = (const float*)d_in[i]; break;
            default: break;
        }
    }
    const float* a_src1 = v64[0]; const float* a_dst1 = v64[1]; const float* b1 = v64[2];
    const float* a_src2 = v64[3]; const float* a_dst2 = v64[4]; const float* b2 = v64[5];
    const float* gamma = v64[6];  const float* beta = v64[7];
    float* out = (float*)d_out;

    const int NB_N  = (NN + SB - 1) / SB;    // 196
    const int NB_E  = (NE + SB - 1) / SB;    // 6250
    const int NB_CSR = (NN + 15) / 16;       // 6250 (16 dst per block)

    // ---- build CSR (dst-sorted adjacency) once; reused by both layers ----
    hist_zero_kernel<<<NB_N, SB>>>();
    hist_kernel<<<NB_E, SB>>>(ei);
    scan1_kernel<<<NB_N, SB>>>();
    scan2_kernel<<<1, 256>>>();
    scan3_kernel<<<NB_N, SB>>>();
    fill_kernel<<<NB_E, SB>>>(ei);

    prep_kernel<<<1, 64>>>(W2, a_src2, a_dst2);

    // Layer 1 (2 heads x 32 ch)
    node1_kernel<<<NN / 4, dim3(64, 4)>>>(x, type_ids, type_emb, W1, a_src1, a_dst1);
    edge_csr_kernel<2><<<NB_CSR, 256>>>(b1);

    // Layer 2 (1 head x 64 ch)
    node2_kernel<<<(NN + 63) / 64, 256>>>(W2);
    edge_csr_kernel<1><<<NB_CSR, 256>>>(nullptr);

    // Bias + LayerNorm -> output
    ln_kernel<<<NN / 8, dim3(32, 8)>>>(b2, gamma, beta, out);
}